// round 12
// baseline (speedup 1.0000x reference)
#include <cuda_runtime.h>

// Problem constants (match reference)
#define N_ATOMS   245760
#define N_PAIRS   16777216
#define N_MOLS    4096
#define KE_CONST  138.96f

#define BLOCKS    592
#define THREADS   512

// Replay-safe handshake state (zero-initialized at module load; the last
// finishing block resets both for the next graph replay).
__device__ int g_flag = 0;   // 1 once out[] is initialized by block 0
__device__ int g_done = 0;   // count of blocks that finished flushing

// ---------------------------------------------------------------------------
// chi(d) with the phi(2d) attenuation folded in
// ---------------------------------------------------------------------------
__device__ __forceinline__ float chi_of_d(float d) {
    // phi(u) = 1 - 6u^5 + 15u^4 - 10u^3, u = 2d, zero for u >= 1
    float u  = 2.0f * d;
    float u2 = u * u;
    float u3 = u2 * u;
    float inner = fmaf(-6.0f, u2, fmaf(15.0f, u, -10.0f));
    float phi   = fmaf(u3, inner, 1.0f);
    phi = (u < 1.0f) ? phi : 0.0f;

    float rs = rsqrtf(fmaf(d, d, 1.0f));   // 1/sqrt(d^2+1)
    float rd = __fdividef(1.0f, d);        // 1/d
    return fmaf(phi, rs - rd, rd);         // rd + phi*(rs-rd)
}

// ---------------------------------------------------------------------------
// Fused kernel: block-0 prologue initializes out; R1 hot loop verbatim;
// flag-gated flush epilogue; last block resets handshake state.
// ---------------------------------------------------------------------------
__global__ __launch_bounds__(THREADS, 4)
void coulomb_pairs_kernel(const float* __restrict__ q,
                          const int*   __restrict__ idx_i,
                          const int*   __restrict__ idx_j,
                          const float* __restrict__ d_ij,
                          const int*   __restrict__ seg,
                          const float* __restrict__ pse,
                          float*       __restrict__ out)
{
    __shared__ float acc[N_MOLS];   // 16 KB per-block private histogram

    // Block 0: initialize output = pse * KE, publish via flag.
    if (blockIdx.x == 0) {
        for (int m = threadIdx.x; m < N_MOLS; m += THREADS)
            out[m] = pse[m] * KE_CONST;
        __threadfence();
        __syncthreads();
        if (threadIdx.x == 0) atomicExch(&g_flag, 1);
    }

    // Vectorized histogram zero (2 x STS.128 per thread)
    {
        float4* acc4 = reinterpret_cast<float4*>(acc);
        for (int m = threadIdx.x; m < N_MOLS / 4; m += THREADS)
            acc4[m] = make_float4(0.0f, 0.0f, 0.0f, 0.0f);
    }
    __syncthreads();

    const int nquads = N_PAIRS / 4;
    const int stride = gridDim.x * THREADS;

    for (int t = blockIdx.x * THREADS + threadIdx.x; t < nquads; t += stride) {
        // ---- Streaming loads (evict-first: keep L1 for gathers) ----
        int4   vi = __ldcs(reinterpret_cast<const int4*>(idx_i) + t);
        int4   vj = __ldcs(reinterpret_cast<const int4*>(idx_j) + t);
        float4 vd = __ldcs(reinterpret_cast<const float4*>(d_ij) + t);
        int4   vs = __ldcs(reinterpret_cast<const int4*>(seg)   + t);

        // ---- Batch the 8 random gathers back-to-back (max MLP) ----
        float qi0 = __ldg(q + vi.x), qj0 = __ldg(q + vj.x);
        float qi1 = __ldg(q + vi.y), qj1 = __ldg(q + vj.y);
        float qi2 = __ldg(q + vi.z), qj2 = __ldg(q + vj.z);
        float qi3 = __ldg(q + vi.w), qj3 = __ldg(q + vj.w);

        // ---- Compute ----
        float c0 = qi0 * qj0 * chi_of_d(vd.x);
        float c1 = qi1 * qj1 * chi_of_d(vd.y);
        float c2 = qi2 * qj2 * chi_of_d(vd.z);
        float c3 = qi3 * qj3 * chi_of_d(vd.w);

        // ---- Scatter: single-statement if -> @P ATOMS (no BSSY) ----
        if (vi.x < vj.x) atomicAdd(&acc[vs.x], c0);
        if (vi.y < vj.y) atomicAdd(&acc[vs.y], c1);
        if (vi.z < vj.z) atomicAdd(&acc[vs.z], c2);
        if (vi.w < vj.w) atomicAdd(&acc[vs.w], c3);
    }

    __syncthreads();

    // Gate on out[] being initialized. In practice the flag was set ~100us
    // ago, so this is a single L2 read per block, never a contended spin.
    if (threadIdx.x == 0) {
        while (atomicOr(&g_flag, 0) == 0) { __nanosleep(64); }
    }
    __syncthreads();

    // Flush block-private histogram (out holds pse*KE).
    for (int m = threadIdx.x; m < N_MOLS; m += THREADS) {
        float v = acc[m];
        if (v != 0.0f)
            atomicAdd(&out[m], v * KE_CONST);
    }

    // Last block resets handshake state for the next graph replay.
    if (threadIdx.x == 0) {
        __threadfence();
        int d = atomicAdd(&g_done, 1);
        if (d == (int)gridDim.x - 1) {
            atomicExch(&g_done, 0);
            atomicExch(&g_flag, 0);
        }
    }
}

// ---------------------------------------------------------------------------
// Launch — single kernel, single wave
// ---------------------------------------------------------------------------
extern "C" void kernel_launch(void* const* d_in, const int* in_sizes, int n_in,
                              void* d_out, int out_size) {
    const float* q    = (const float*)d_in[0];           // per_atom_charge [N_ATOMS]
    const int*   pidx = (const int*)  d_in[1];           // pair_indices [2, N_PAIRS]
    const float* dij  = (const float*)d_in[2];           // d_ij [N_PAIRS]
    const int*   seg  = (const int*)  d_in[3];           // atomic_subsystem_indices [N_PAIRS]
    const float* pse  = (const float*)d_in[4];           // per_system_energy [N_MOLS]
    float* out = (float*)d_out;

    const int* idx_i = pidx;
    const int* idx_j = pidx + N_PAIRS;

    coulomb_pairs_kernel<<<BLOCKS, THREADS>>>(q, idx_i, idx_j, dij, seg, pse, out);
}

// round 13
// speedup vs baseline: 1.6670x; 1.6670x over previous
#include <cuda_runtime.h>

// Problem constants (match reference)
#define N_ATOMS   245760
#define N_PAIRS   16777216
#define N_MOLS    4096
#define KE_CONST  138.96f

// ---------------------------------------------------------------------------
// Kernel 1: initialize output with per_system_energy * KE
// ---------------------------------------------------------------------------
__global__ void init_out_kernel(const float* __restrict__ pse,
                                float* __restrict__ out) {
    int m = blockIdx.x * blockDim.x + threadIdx.x;
    if (m < N_MOLS) out[m] = pse[m] * KE_CONST;
}

// ---------------------------------------------------------------------------
// Kernel 2: main pair loop with SMEM-privatized segment accumulation
// ---------------------------------------------------------------------------
__device__ __forceinline__ void process_pair(
    const float* __restrict__ q,
    int i, int j, float d, int s,
    float* __restrict__ acc)
{
    // Gather charges (random access; let these use L1/L2 default caching)
    float qi = __ldg(q + i);
    float qj = __ldg(q + j);

    // phi(2d) = 1 - 6u^5 + 15u^4 - 10u^3 with u = 2d, valid for u < 1
    float u  = 2.0f * d;
    float u2 = u * u;
    float u3 = u2 * u;
    // inner = -6u^2 + 15u - 10
    float inner = fmaf(-6.0f, u2, fmaf(15.0f, u, -10.0f));
    float phi   = fmaf(u3, inner, 1.0f);
    phi = (u < 1.0f) ? phi : 0.0f;

    // chi = phi / sqrt(d^2+1) + (1-phi)/d  ==  rd + phi*(rs - rd)
    float rs = rsqrtf(fmaf(d, d, 1.0f));     // MUFU.RSQ
    float rd = __fdividef(1.0f, d);          // MUFU.RCP (approx)
    float chi = fmaf(phi, rs - rd, rd);

    if (i < j) {
        atomicAdd(&acc[s], qi * qj * chi);
    }
}

__global__ __launch_bounds__(512)
void coulomb_pairs_kernel(const float* __restrict__ q,
                          const int*   __restrict__ idx_i,
                          const int*   __restrict__ idx_j,
                          const float* __restrict__ d_ij,
                          const int*   __restrict__ seg,
                          float*       __restrict__ out)
{
    __shared__ float acc[N_MOLS];   // 16 KB per-block private histogram

    for (int m = threadIdx.x; m < N_MOLS; m += blockDim.x)
        acc[m] = 0.0f;
    __syncthreads();

    const int nquads = N_PAIRS / 4;
    const int stride = gridDim.x * blockDim.x;

    for (int t = blockIdx.x * blockDim.x + threadIdx.x; t < nquads; t += stride) {
        // Streaming loads, evict-first so the charge table keeps L1
        int4   vi = __ldcs(reinterpret_cast<const int4*>(idx_i) + t);
        int4   vj = __ldcs(reinterpret_cast<const int4*>(idx_j) + t);
        float4 vd = __ldcs(reinterpret_cast<const float4*>(d_ij) + t);
        int4   vs = __ldcs(reinterpret_cast<const int4*>(seg)   + t);

        process_pair(q, vi.x, vj.x, vd.x, vs.x, acc);
        process_pair(q, vi.y, vj.y, vd.y, vs.y, acc);
        process_pair(q, vi.z, vj.z, vd.z, vs.z, acc);
        process_pair(q, vi.w, vj.w, vd.w, vs.w, acc);
    }

    __syncthreads();

    // Flush block-private histogram to global (already holds pse*KE)
    for (int m = threadIdx.x; m < N_MOLS; m += blockDim.x) {
        float v = acc[m];
        if (v != 0.0f)
            atomicAdd(&out[m], v * KE_CONST);
    }
}

// ---------------------------------------------------------------------------
// Launch
// ---------------------------------------------------------------------------
extern "C" void kernel_launch(void* const* d_in, const int* in_sizes, int n_in,
                              void* d_out, int out_size) {
    const float* q    = (const float*)d_in[0];           // per_atom_charge [N_ATOMS]
    const int*   pidx = (const int*)  d_in[1];           // pair_indices [2, N_PAIRS]
    const float* dij  = (const float*)d_in[2];           // d_ij [N_PAIRS]
    const int*   seg  = (const int*)  d_in[3];           // atomic_subsystem_indices [N_PAIRS]
    const float* pse  = (const float*)d_in[4];           // per_system_energy [N_MOLS]
    float* out = (float*)d_out;

    const int* idx_i = pidx;
    const int* idx_j = pidx + N_PAIRS;

    init_out_kernel<<<(N_MOLS + 255) / 256, 256>>>(pse, out);

    // 4 blocks/SM x 148 SMs, 512 threads — 16 KB SMEM/block histogram
    const int blocks  = 592;
    const int threads = 512;
    coulomb_pairs_kernel<<<blocks, threads>>>(q, idx_i, idx_j, dij, seg, out);
}

// round 14
// speedup vs baseline: 1.6782x; 1.0067x over previous
#include <cuda_runtime.h>

// Problem constants (match reference)
#define N_ATOMS   245760
#define N_PAIRS   16777216
#define N_MOLS    4096
#define KE_CONST  138.96f

// ---------------------------------------------------------------------------
// chi(d) with the phi(2d) attenuation folded in
// ---------------------------------------------------------------------------
__device__ __forceinline__ void process_pair(
    const float* __restrict__ q,
    int i, int j, float d, int s,
    float* __restrict__ acc)
{
    // Gather charges (random access; L1/L2 default caching)
    float qi = __ldg(q + i);
    float qj = __ldg(q + j);

    // phi(2d) = 1 - 6u^5 + 15u^4 - 10u^3 with u = 2d, valid for u < 1
    float u  = 2.0f * d;
    float u2 = u * u;
    float u3 = u2 * u;
    float inner = fmaf(-6.0f, u2, fmaf(15.0f, u, -10.0f));
    float phi   = fmaf(u3, inner, 1.0f);
    phi = (u < 1.0f) ? phi : 0.0f;

    // chi = phi / sqrt(d^2+1) + (1-phi)/d  ==  rd + phi*(rs - rd)
    float rs = rsqrtf(fmaf(d, d, 1.0f));     // MUFU.RSQ
    float rd = __fdividef(1.0f, d);          // MUFU.RCP (approx)
    float chi = fmaf(phi, rs - rd, rd);

    if (i < j) {
        atomicAdd(&acc[s], qi * qj * chi);
    }
}

// ---------------------------------------------------------------------------
// Single fused kernel: block 0 initializes out in its prologue (single wave
// + ~127us main loop gives a >100x timing margin before any flush atomic);
// hot loop and epilogue byte-identical to the measured-best R1/R13 kernel.
// ---------------------------------------------------------------------------
__global__ __launch_bounds__(512)
void coulomb_pairs_kernel(const float* __restrict__ q,
                          const int*   __restrict__ idx_i,
                          const int*   __restrict__ idx_j,
                          const float* __restrict__ d_ij,
                          const int*   __restrict__ seg,
                          const float* __restrict__ pse,
                          float*       __restrict__ out)
{
    __shared__ float acc[N_MOLS];   // 16 KB per-block private histogram

    // Block 0 prologue: out = pse * KE (8 coalesced STG iterations, <1us;
    // global stores are write-through to L2 where the flush atomics operate).
    if (blockIdx.x == 0) {
        for (int m = threadIdx.x; m < N_MOLS; m += blockDim.x)
            out[m] = pse[m] * KE_CONST;
    }

    for (int m = threadIdx.x; m < N_MOLS; m += blockDim.x)
        acc[m] = 0.0f;
    __syncthreads();

    const int nquads = N_PAIRS / 4;
    const int stride = gridDim.x * blockDim.x;

    for (int t = blockIdx.x * blockDim.x + threadIdx.x; t < nquads; t += stride) {
        // Streaming loads, evict-first so the charge table keeps L1
        int4   vi = __ldcs(reinterpret_cast<const int4*>(idx_i) + t);
        int4   vj = __ldcs(reinterpret_cast<const int4*>(idx_j) + t);
        float4 vd = __ldcs(reinterpret_cast<const float4*>(d_ij) + t);
        int4   vs = __ldcs(reinterpret_cast<const int4*>(seg)   + t);

        process_pair(q, vi.x, vj.x, vd.x, vs.x, acc);
        process_pair(q, vi.y, vj.y, vd.y, vs.y, acc);
        process_pair(q, vi.z, vj.z, vd.z, vs.z, acc);
        process_pair(q, vi.w, vj.w, vd.w, vs.w, acc);
    }

    __syncthreads();

    // Flush block-private histogram to global (out already holds pse*KE;
    // block 0 wrote it ~127us ago — far beyond any visibility latency).
    for (int m = threadIdx.x; m < N_MOLS; m += blockDim.x) {
        float v = acc[m];
        if (v != 0.0f)
            atomicAdd(&out[m], v * KE_CONST);
    }
}

// ---------------------------------------------------------------------------
// Launch — single kernel, single wave
// ---------------------------------------------------------------------------
extern "C" void kernel_launch(void* const* d_in, const int* in_sizes, int n_in,
                              void* d_out, int out_size) {
    const float* q    = (const float*)d_in[0];           // per_atom_charge [N_ATOMS]
    const int*   pidx = (const int*)  d_in[1];           // pair_indices [2, N_PAIRS]
    const float* dij  = (const float*)d_in[2];           // d_ij [N_PAIRS]
    const int*   seg  = (const int*)  d_in[3];           // atomic_subsystem_indices [N_PAIRS]
    const float* pse  = (const float*)d_in[4];           // per_system_energy [N_MOLS]
    float* out = (float*)d_out;

    const int* idx_i = pidx;
    const int* idx_j = pidx + N_PAIRS;

    // 4 blocks/SM x 148 SMs, 512 threads — 16 KB SMEM/block histogram
    const int blocks  = 592;
    const int threads = 512;
    coulomb_pairs_kernel<<<blocks, threads>>>(q, idx_i, idx_j, dij, seg, pse, out);
}